// round 5
// baseline (speedup 1.0000x reference)
#include <cuda_runtime.h>
#include <cstdint>

#define BB 128
#define SS 4096
#define TT 64

// Scratch (no cudaMalloc allowed)
__device__ float g_num[BB];
__device__ float g_den[BB];
__device__ int   g_len[BB];

// ---------------- packed f32x2 helpers ----------------
__device__ __forceinline__ unsigned long long pack2(float lo, float hi) {
    unsigned long long r;
    asm("mov.b64 %0, {%1, %2};" : "=l"(r) : "f"(lo), "f"(hi));
    return r;
}
__device__ __forceinline__ void unpack2(unsigned long long p, float& lo, float& hi) {
    asm("mov.b64 {%0, %1}, %2;" : "=f"(lo), "=f"(hi) : "l"(p));
}
__device__ __forceinline__ void fma2(unsigned long long& d, unsigned long long a, unsigned long long b) {
    asm("fma.rn.f32x2 %0, %1, %2, %0;" : "+l"(d) : "l"(a), "l"(b));
}
__device__ __forceinline__ unsigned long long mul2(unsigned long long a, unsigned long long b) {
    unsigned long long d;
    asm("mul.rn.f32x2 %0, %1, %2;" : "=l"(d) : "l"(a), "l"(b));
    return d;
}
__device__ __forceinline__ unsigned long long add2(unsigned long long a, unsigned long long b) {
    unsigned long long d;
    asm("add.rn.f32x2 %0, %1, %2;" : "=l"(d) : "l"(a), "l"(b));
    return d;
}

// ---------------- kernel 1: numerator + lengths ----------------
// mask dtype can be bool(uint8) or int32 depending on serialization; detect:
// mask[0] is always true (L >= S/2). uint8 layout -> first int32 word = 0x01010101,
// int32 layout -> first word = 1.
__global__ void crf_numer_kernel(const float* __restrict__ logits,
                                 const int* __restrict__ tags,
                                 const void* __restrict__ mask,
                                 const float* __restrict__ trans,
                                 const float* __restrict__ start_t,
                                 const float* __restrict__ end_t) {
    const int b = blockIdx.x;
    const int tid = threadIdx.x;
    const int NT = 256;

    const bool m32 = (((const int*)mask)[0] == 1);
    const float* lg = logits + (size_t)b * SS * TT;
    const int* tg = tags + b * SS;
    const unsigned char* mk8 = ((const unsigned char*)mask) + (size_t)b * SS;
    const int* mk32 = ((const int*)mask) + (size_t)b * SS;

    float sum = 0.f;
    int cnt = 0;
    for (int t = tid; t < SS; t += NT) {
        int m = m32 ? (mk32[t] != 0) : (mk8[t] != 0);
        cnt += m;
        if (m) {
            int tagt = tg[t];
            sum += lg[(size_t)t * TT + tagt];
            if (t > 0) sum += trans[tg[t - 1] * TT + tagt];
        }
    }
#pragma unroll
    for (int o = 16; o > 0; o >>= 1) {
        sum += __shfl_down_sync(0xffffffffu, sum, o);
        cnt += __shfl_down_sync(0xffffffffu, cnt, o);
    }
    __shared__ float ssum[8];
    __shared__ int scnt[8];
    if ((tid & 31) == 0) { ssum[tid >> 5] = sum; scnt[tid >> 5] = cnt; }
    __syncthreads();
    if (tid == 0) {
        float s2 = 0.f; int c2 = 0;
#pragma unroll
        for (int w = 0; w < 8; w++) { s2 += ssum[w]; c2 += scnt[w]; }
        int L = c2;
        s2 += start_t[tg[0]] + end_t[tg[L - 1]];
        g_num[b] = s2;
        g_len[b] = L;
    }
}

// ---------------- kernel 2: forward scan (denominator) ----------------
__device__ __forceinline__ void crf_step(const unsigned long long (&e2)[32],
                                         const float* ubuf_r, float* ubuf_w,
                                         int j, float lval, float& v, float& C) {
    __syncthreads();
    // Broadcast-load previous u (64 floats) as 32 f32x2 pairs via LDS.128
    unsigned long long uu[32];
#pragma unroll
    for (int q = 0; q < 16; q++) {
        ulonglong2 p = *reinterpret_cast<const ulonglong2*>(ubuf_r + 4 * q);
        uu[2 * q]     = p.x;
        uu[2 * q + 1] = p.y;
    }
    float u0 = __uint_as_float((unsigned)uu[0]);
    float r;
    asm("rcp.approx.f32 %0, %1;" : "=f"(r) : "f"(u0));
    float gex = __expf(lval);
    float gr = gex * r;
    C = fmaf(__log2f(u0), 0.6931471805599453f, C);

    unsigned long long a0 = mul2(uu[0], e2[0]);
    unsigned long long a1 = mul2(uu[1], e2[1]);
    unsigned long long a2 = mul2(uu[2], e2[2]);
    unsigned long long a3 = mul2(uu[3], e2[3]);
#pragma unroll
    for (int i = 4; i < 32; i += 4) {
        fma2(a0, uu[i],     e2[i]);
        fma2(a1, uu[i + 1], e2[i + 1]);
        fma2(a2, uu[i + 2], e2[i + 2]);
        fma2(a3, uu[i + 3], e2[i + 3]);
    }
    a0 = add2(a0, a1);
    a2 = add2(a2, a3);
    a0 = add2(a0, a2);
    float lo, hi;
    unpack2(a0, lo, hi);
    v = (lo + hi) * gr;
    ubuf_w[j] = v;
}

__global__ void __launch_bounds__(64, 1)
crf_scan_kernel(const float* __restrict__ logits,
                const float* __restrict__ trans,
                const float* __restrict__ start_t,
                const float* __restrict__ end_t) {
    const int b = blockIdx.x;
    const int j = threadIdx.x;
    const float* lg = logits + (size_t)b * SS * TT;
    const int L = g_len[b];

    // E column j = exp(trans[:, j]) packed along i into f32x2
    unsigned long long e2[32];
#pragma unroll
    for (int i2 = 0; i2 < 32; i2++) {
        float a = __expf(trans[(2 * i2) * TT + j]);
        float c = __expf(trans[(2 * i2 + 1) * TT + j]);
        e2[i2] = pack2(a, c);
    }

    __shared__ __align__(16) float ubuf[2][TT];
    __shared__ float zz[2];

    // alpha0 = start + logits[:,0]  (linear domain)
    float v = __expf(start_t[j] + lg[j]);
    ubuf[1][j] = v;   // iteration t reads ubuf[t & 1]; t starts at 1
    float C = 0.f;

    // 8-deep register prefetch queue of logits[t][j]
    float lq[8];
#pragma unroll
    for (int k = 0; k < 8; k++)
        lq[k] = lg[(size_t)(1 + k) * TT + j];

    int t = 1;
    for (; t + 8 <= L; t += 8) {
#pragma unroll
        for (int k = 0; k < 8; k++) {
            const int rb = (1 + k) & 1;  // t is always odd here
            crf_step(e2, ubuf[rb], ubuf[rb ^ 1], j, lq[k], v, C);
            int nt = t + k + 8;
            nt = (nt < SS - 1) ? nt : (SS - 1);
            lq[k] = lg[(size_t)nt * TT + j];
        }
    }
    {
        const int rem = L - t;
#pragma unroll
        for (int k = 0; k < 8; k++) {
            if (k < rem) {
                const int rb = (1 + k) & 1;  // t still odd
                crf_step(e2, ubuf[rb], ubuf[rb ^ 1], j, lq[k], v, C);
            }
        }
    }

    // den = C + log( sum_j v_j * exp(end_j) )
    float z = v * __expf(end_t[j]);
#pragma unroll
    for (int o = 16; o > 0; o >>= 1)
        z += __shfl_down_sync(0xffffffffu, z, o);
    if ((j & 31) == 0) zz[j >> 5] = z;
    __syncthreads();
    if (j == 0) {
        g_den[b] = C + __logf(zz[0] + zz[1]);
    }
}

// ---------------- kernel 3: deterministic final reduction ----------------
__global__ void crf_finish_kernel(float* __restrict__ out) {
    const int i = threadIdx.x;  // 128 threads
    float d = g_num[i] - g_den[i];
#pragma unroll
    for (int o = 16; o > 0; o >>= 1)
        d += __shfl_down_sync(0xffffffffu, d, o);
    __shared__ float ws[4];
    if ((i & 31) == 0) ws[i >> 5] = d;
    __syncthreads();
    if (i == 0) out[0] = (ws[0] + ws[1]) + (ws[2] + ws[3]);
}

// ---------------- launch ----------------
extern "C" void kernel_launch(void* const* d_in, const int* in_sizes, int n_in,
                              void* d_out, int out_size) {
    const float* logits = (const float*)d_in[0];
    const int* tags     = (const int*)d_in[1];
    const void* mask    = d_in[2];
    const float* trans  = (const float*)d_in[3];
    const float* startt = (const float*)d_in[4];
    const float* endt   = (const float*)d_in[5];
    float* out = (float*)d_out;

    crf_numer_kernel<<<BB, 256>>>(logits, tags, mask, trans, startt, endt);
    crf_scan_kernel<<<BB, 64>>>(logits, trans, startt, endt);
    crf_finish_kernel<<<1, 128>>>(out);
}